// round 5
// baseline (speedup 1.0000x reference)
#include <cuda_runtime.h>
#include <cuda_fp16.h>
#include <cstddef>

#define D 64
#define NH 4
#define DH 16
#define FF 2048
#define VV 1000000
#define STEPS 10
#define EPS 1e-5f
#define NB 148
#define NT 512
#define PB 32  // blocks running P1/P2

// Persistent device state (reset by block 0 each call, guarded by init barrier).
__device__ float g_y0[STEPS * D];     // ffn0 accumulator (atomicAdd)
__device__ float g_x1b[D];            // layer-1 post-LN1, last row
__device__ float g_y1part[PB * D];    // ffn1 per-block partials (no reset needed)
__device__ float g_xf[D];             // final LN'd x (published with ready flag)
__device__ unsigned long long g_amax[STEPS];
__device__ int g_gen[STEPS];
__device__ uint4 g_embh4[VV * 8];     // fp16 emb copy (written step 0)
__device__ int g_cnt, g_genbar;       // init full barrier
__device__ int g_done;                // cumulative scan-done counter
__device__ int g_mini;                // cumulative P1->P2 mini barrier (32 blocks)
__device__ int g_p2c;                 // cumulative P2-done counter
__device__ int g_ready;               // step ready flag (== t+1 when xf ready)
__device__ int g_pos[STEPS];          // work-stealing position per step

__device__ __forceinline__ unsigned int fkey(float f) {
    unsigned int u = __float_as_uint(f);
    return (u & 0x80000000u) ? ~u : (u | 0x80000000u);
}
__device__ __forceinline__ int dec_idx(unsigned long long k) {
    return (int)(0xFFFFFFFFu - (unsigned int)(k & 0xFFFFFFFFull));
}
__device__ __forceinline__ float dot4(float4 a, float4 b) {
    return a.x * b.x + a.y * b.y + a.z * b.z + a.w * b.w;
}
__device__ __forceinline__ uint4 pack8(float4 a, float4 b) {
    uint4 o;
    __half2 h;
    h = __floats2half2_rn(a.x, a.y); o.x = *(unsigned int*)&h;
    h = __floats2half2_rn(a.z, a.w); o.y = *(unsigned int*)&h;
    h = __floats2half2_rn(b.x, b.y); o.z = *(unsigned int*)&h;
    h = __floats2half2_rn(b.z, b.w); o.w = *(unsigned int*)&h;
    return o;
}
__device__ __forceinline__ float dot8h(uint4 q, float4 xa, float4 xb) {
    __half2* hp = (__half2*)&q;
    float2 f0 = __half22float2(hp[0]), f1 = __half22float2(hp[1]);
    float2 f2 = __half22float2(hp[2]), f3 = __half22float2(hp[3]);
    return f0.x * xa.x + f0.y * xa.y + f1.x * xa.z + f1.y * xa.w
         + f2.x * xb.x + f2.y * xb.y + f3.x * xb.z + f3.y * xb.w;
}
__device__ __forceinline__ float red8(float v) {
    v += __shfl_xor_sync(0xffffffffu, v, 4);
    v += __shfl_xor_sync(0xffffffffu, v, 2);
    v += __shfl_xor_sync(0xffffffffu, v, 1);
    return v;
}

// Full grid barrier -- used ONCE at init.
__device__ __forceinline__ void grid_bar() {
    __syncthreads();
    if (threadIdx.x == 0) {
        volatile int* genp = &g_genbar;
        int gen = *genp;
        __threadfence();
        if (atomicAdd(&g_cnt, 1) == NB - 1) {
            atomicExch(&g_cnt, 0);
            __threadfence();
            *genp = gen + 1;
        } else {
            while (*genp == gen) { __nanosleep(32); }
        }
    }
    __syncthreads();
}

__global__ void __launch_bounds__(NT, 1)
persist_kernel(const float* __restrict__ ht, const float* __restrict__ emb,
               const float* __restrict__ pos, const float* __restrict__ ipw,
               const float* __restrict__ ipb, const float* __restrict__ ow,
               const float* __restrict__ ob, const float* __restrict__ ln1w,
               const float* __restrict__ ln1b, const float* __restrict__ ln2w,
               const float* __restrict__ ln2b, const float* __restrict__ f1w,
               const float* __restrict__ f1b, const float* __restrict__ f2w,
               const float* __restrict__ f2b, float* __restrict__ out,
               int out_size) {
    __shared__ __align__(16) float sA[STEPS * D];
    __shared__ __align__(16) float sQ[STEPS * 3 * D];
    __shared__ __align__(16) float sO[STEPS * D];
    __shared__ float sSC[NH * STEPS * STEPS];
    __shared__ float sST[2 * STEPS + 4];
    __shared__ int sgen[STEPS];
    __shared__ int s_last;
    __shared__ unsigned long long sbs[NT];

    const int tid = threadIdx.x, blk = blockIdx.x;
    const int lane = tid & 31;
    const int grp = lane >> 3, l8 = lane & 7;
    const int g8 = tid >> 3, r8 = tid & 7;

    // ---- init (block 0), then one full barrier ----
    if (blk == 0) {
        if (tid == 0) { g_done = 0; g_mini = 0; g_p2c = 0; g_ready = 0; }
        if (tid < STEPS) { g_pos[tid] = 0; g_amax[tid] = 0ull; }
        for (int i = tid; i < STEPS * D; i += NT) g_y0[i] = 0.f;
        __threadfence();
    }
    grid_bar();

    for (int t = 0; t < STEPS; t++) {
        const int S = t + 1;

        if (blk < PB) {
            // wait for all scans of step t-1
            if (t > 0) {
                if (tid == 0)
                    while (*(volatile int*)&g_done < NB * t) __nanosleep(64);
                __syncthreads();
            }
            // ---------------- P1: layer-0 attn (redundant) + ffn0 slice ----
            if (tid < t) {
                int gi;
                if (tid == t - 1) {
                    gi = dec_idx(__ldcg(&g_amax[t - 1]));
                    if (blk == 0) __stcg(&g_gen[t - 1], gi);
                } else {
                    gi = __ldcg(&g_gen[tid]);
                }
                sgen[tid] = gi;
            }
            __syncthreads();
            for (int i = tid; i < S * D; i += NT) {
                int s = i >> 6, d = i & 63;
                float base = (s == 0) ? ht[d] : emb[(size_t)sgen[s - 1] * D + d];
                sA[i] = base + pos[i];
            }
            __syncthreads();
            for (int i = tid; i < S * 3 * D; i += NT) {
                int s = i / 192, j = i % 192;
                const float4* wr = (const float4*)(ipw + (size_t)j * D);
                const float4* xr = (const float4*)(sA + s * D);
                float acc = ipb[j];
#pragma unroll
                for (int k = 0; k < 16; k++) acc += dot4(wr[k], xr[k]);
                sQ[i] = acc;
            }
            __syncthreads();
            for (int i = tid; i < NH * S * S; i += NT) {
                int h = i / (S * S), r = (i / S) % S, c = i % S;
                const float* q = sQ + r * 192 + h * DH;
                const float* k = sQ + c * 192 + D + h * DH;
                float acc = 0.f;
#pragma unroll
                for (int d = 0; d < DH; d++) acc += q[d] * k[d];
                sSC[(h * S + r) * S + c] = acc * 0.25f;
            }
            __syncthreads();
            if (tid < NH * S) {
                float* row = sSC + tid * S;
                float mx = row[0];
                for (int c = 1; c < S; c++) mx = fmaxf(mx, row[c]);
                float sm = 0.f;
                for (int c = 0; c < S; c++) { float e = expf(row[c] - mx); row[c] = e; sm += e; }
                float inv = 1.f / sm;
                for (int c = 0; c < S; c++) row[c] *= inv;
            }
            __syncthreads();
            for (int i = tid; i < S * D; i += NT) {
                int s = i >> 6, col = i & 63, h = col >> 4, d = col & 15;
                const float* a = sSC + (h * S + s) * S;
                float acc = 0.f;
                for (int c = 0; c < S; c++) acc += a[c] * sQ[c * 192 + 2 * D + h * DH + d];
                sO[i] = acc;
            }
            __syncthreads();
            for (int i = tid; i < S * D; i += NT) {
                int s = i >> 6, e = i & 63;
                const float4* wr = (const float4*)(ow + (size_t)e * D);
                const float4* orow = (const float4*)(sO + s * D);
                float acc = ob[e];
#pragma unroll
                for (int k = 0; k < 16; k++) acc += dot4(wr[k], orow[k]);
                sQ[i] = sA[i] + acc;
            }
            __syncthreads();
            if (tid < S) {
                float m = 0.f;
                for (int d = 0; d < D; d++) m += sQ[tid * D + d];
                m *= (1.f / D);
                float vv = 0.f;
                for (int d = 0; d < D; d++) { float df = sQ[tid * D + d] - m; vv += df * df; }
                vv *= (1.f / D);
                sST[tid * 2] = m;
                sST[tid * 2 + 1] = rsqrtf(vv + EPS);
            }
            __syncthreads();
            for (int i = tid; i < S * D; i += NT) {
                int s = i >> 6, d = i & 63;
                sA[i] = (sQ[i] - sST[s * 2]) * sST[s * 2 + 1] * ln1w[d] + ln1b[d];
            }
            __syncthreads();
            {   // ffn0: 64 units per block
                int f = blk * 64 + g8;
                const float4* w1r = (const float4*)(f1w + (size_t)f * D);
                float4 wa = w1r[2 * r8], wb = w1r[2 * r8 + 1];
                float b1 = f1b[f];
                const float4* x4 = (const float4*)sA;
                for (int s = 0; s < S; s++) {
                    float v = red8(dot4(wa, x4[s * 16 + 2 * r8]) + dot4(wb, x4[s * 16 + 2 * r8 + 1]));
                    if (r8 == 0) sO[s * 64 + g8] = fmaxf(v + b1, 0.f);
                }
                __syncthreads();
                const float4* w2r = (const float4*)(f2w + (size_t)g8 * FF + blk * 64);
                float4 va = w2r[2 * r8], vb = w2r[2 * r8 + 1];
                const float4* h4 = (const float4*)sO;
                for (int s = 0; s < S; s++) {
                    float r = red8(dot4(va, h4[s * 16 + 2 * r8]) + dot4(vb, h4[s * 16 + 2 * r8 + 1]));
                    if (r8 == 0) atomicAdd(&g_y0[s * 64 + g8], r);
                }
            }
            // ---- mini barrier among the 32 P blocks ----
            __threadfence();
            __syncthreads();
            if (tid == 0) {
                atomicAdd(&g_mini, 1);
                while (*(volatile int*)&g_mini < PB * (t + 1)) __nanosleep(32);
            }
            __syncthreads();

            // ---------------- P2: layer-1 attn last-row (redundant) + ffn1 slice
            for (int i = tid; i < S * D; i += NT) {
                float b0 = (blk == 0) ? 0.f : 0.f;  // bias folded below
                sA[i] = sA[i] + __ldcg(&g_y0[i]) + f2b[i & 63];
            }
            __syncthreads();
            if (tid < S) {
                float m = 0.f;
                for (int d = 0; d < D; d++) m += sA[tid * D + d];
                m *= (1.f / D);
                float vv = 0.f;
                for (int d = 0; d < D; d++) { float df = sA[tid * D + d] - m; vv += df * df; }
                vv *= (1.f / D);
                sST[tid * 2] = m;
                sST[tid * 2 + 1] = rsqrtf(vv + EPS);
            }
            __syncthreads();
            for (int i = tid; i < S * D; i += NT) {
                int s = i >> 6, d = i & 63;
                sA[i] = (sA[i] - sST[s * 2]) * sST[s * 2 + 1] * ln2w[d] + ln2b[d];
            }
            __syncthreads();
            for (int i = tid; i < S * 3 * D; i += NT) {
                int s = i / 192, j = i % 192;
                const float4* wr = (const float4*)(ipw + (size_t)(192 + j) * D);
                const float4* xr = (const float4*)(sA + s * D);
                float acc = ipb[192 + j];
#pragma unroll
                for (int k = 0; k < 16; k++) acc += dot4(wr[k], xr[k]);
                sQ[i] = acc;
            }
            __syncthreads();
            if (tid < NH * S) {
                int h = tid / S, c = tid % S;
                const float* q = sQ + (S - 1) * 192 + h * DH;
                const float* k = sQ + c * 192 + D + h * DH;
                float acc = 0.f;
#pragma unroll
                for (int d = 0; d < DH; d++) acc += q[d] * k[d];
                sSC[h * S + c] = acc * 0.25f;
            }
            __syncthreads();
            if (tid < NH) {
                float* row = sSC + tid * S;
                float mx = row[0];
                for (int c = 1; c < S; c++) mx = fmaxf(mx, row[c]);
                float sm = 0.f;
                for (int c = 0; c < S; c++) { float e = expf(row[c] - mx); row[c] = e; sm += e; }
                float inv = 1.f / sm;
                for (int c = 0; c < S; c++) row[c] *= inv;
            }
            __syncthreads();
            if (tid < D) {
                int h = tid >> 4, d = tid & 15;
                const float* a = sSC + h * S;
                float acc = 0.f;
                for (int c = 0; c < S; c++) acc += a[c] * sQ[c * 192 + 2 * D + h * DH + d];
                sO[tid] = acc;
            }
            __syncthreads();
            if (tid < D) {
                const float4* wr = (const float4*)(ow + (size_t)(D + tid) * D);
                const float4* orow = (const float4*)sO;
                float acc = ob[D + tid];
#pragma unroll
                for (int k = 0; k < 16; k++) acc += dot4(wr[k], orow[k]);
                sQ[tid] = sA[(S - 1) * D + tid] + acc;
            }
            __syncthreads();
            if (tid == 0) {
                float m = 0.f;
                for (int d = 0; d < D; d++) m += sQ[d];
                m *= (1.f / D);
                float vv = 0.f;
                for (int d = 0; d < D; d++) { float df = sQ[d] - m; vv += df * df; }
                vv *= (1.f / D);
                sST[20] = m;
                sST[21] = rsqrtf(vv + EPS);
            }
            __syncthreads();
            if (tid < D) {
                float xl = (sQ[tid] - sST[20]) * sST[21] * ln1w[D + tid] + ln1b[D + tid];
                sA[tid] = xl;
                if (blk == 0) __stcg(&g_x1b[tid], xl);
            }
            __syncthreads();
            {   // ffn1 (layer 1), last row only -> per-block partial
                int f = blk * 64 + g8;
                const float4* w1r = (const float4*)(f1w + (size_t)FF * D + (size_t)f * D);
                float4 wa = w1r[2 * r8], wb = w1r[2 * r8 + 1];
                const float4* x4 = (const float4*)sA;
                float v = red8(dot4(wa, x4[2 * r8]) + dot4(wb, x4[2 * r8 + 1]));
                if (r8 == 0) sO[g8] = fmaxf(v + f1b[FF + f], 0.f);
                __syncthreads();
                const float4* w2r = (const float4*)(f2w + (size_t)D * FF + (size_t)g8 * FF + blk * 64);
                float4 va = w2r[2 * r8], vb = w2r[2 * r8 + 1];
                const float4* h4 = (const float4*)sO;
                float r = red8(dot4(va, h4[2 * r8]) + dot4(vb, h4[2 * r8 + 1]));
                if (r8 == 0) __stcg(&g_y1part[blk * 64 + g8], r);
            }
            // zero g_y0 for next step (this block's slice of rows is overkill; blk0 does all)
            if (blk == 0)
                for (int i = tid; i < STEPS * D; i += NT) __stcg(&g_y0[i], 0.f);
            __threadfence();
            __syncthreads();
            if (tid == 0) s_last = atomicAdd(&g_p2c, 1);
            __syncthreads();
            if (s_last == PB * (t + 1) - 1) {
                // last P2 block: assemble x_final, LN, publish
                if (tid < D) {
                    float v = __ldcg(&g_x1b[tid]) + f2b[D + tid];
#pragma unroll
                    for (int b = 0; b < PB; b++) v += __ldcg(&g_y1part[b * 64 + tid]);
                    sQ[tid] = v;
                }
                __syncthreads();
                if (tid == 0) {
                    float m = 0.f;
                    for (int d = 0; d < D; d++) m += sQ[d];
                    m *= (1.f / D);
                    float vv = 0.f;
                    for (int d = 0; d < D; d++) { float df = sQ[d] - m; vv += df * df; }
                    vv *= (1.f / D);
                    sST[0] = m;
                    sST[1] = rsqrtf(vv + EPS);
                }
                __syncthreads();
                if (tid < D)
                    __stcg(&g_xf[tid], (sQ[tid] - sST[0]) * sST[1] * ln2w[D + tid] + ln2b[D + tid]);
                __threadfence();
                __syncthreads();
                if (tid == 0) atomicExch(&g_ready, t + 1);
            }
        }

        // ================= scan phase (all blocks) =================
        if (tid == 0)
            while (*(volatile int*)&g_ready < t + 1) __nanosleep(64);
        __syncthreads();
        if (tid < D) sO[tid] = __ldcg(&g_xf[tid]);
        __syncthreads();

        const float4* xs4 = (const float4*)sO;
        float4 xa = xs4[2 * l8], xb = xs4[2 * l8 + 1];
        unsigned long long best = 0ull;
        float* orow = out + (size_t)t * VV;

        if (t == 0) {
            // 16 rows per warp unit, grab-ahead stealing
            int u_next;
            if (lane == 0) u_next = atomicAdd(&g_pos[0], 16);
            u_next = __shfl_sync(0xffffffffu, u_next, 0);
            while (u_next < VV) {
                int u = u_next;
                if (lane == 0) u_next = atomicAdd(&g_pos[0], 16);
                u_next = __shfl_sync(0xffffffffu, u_next, 0);
                int v0 = u + grp * 4;
                float4 av[4], bv[4];
#pragma unroll
                for (int r = 0; r < 4; r++) {
                    const float4* p = (const float4*)(emb + (size_t)(v0 + r) * D);
                    av[r] = __ldcg(p + 2 * l8);
                    bv[r] = __ldcg(p + 2 * l8 + 1);
                }
#pragma unroll
                for (int r = 0; r < 4; r++) {
                    int v = v0 + r;
                    __stcg(&g_embh4[(size_t)v * 8 + l8], pack8(av[r], bv[r]));
                    float dot = dot4(av[r], xa) + dot4(bv[r], xb);
                    dot += __shfl_xor_sync(0xffffffffu, dot, 1);
                    dot += __shfl_xor_sync(0xffffffffu, dot, 2);
                    dot += __shfl_xor_sync(0xffffffffu, dot, 4);
                    if (l8 == 0) {
                        __stcg(&orow[v], dot);
                        unsigned long long key =
                            ((unsigned long long)fkey(dot) << 32) | (0xFFFFFFFFu - (unsigned)v);
                        if (key > best) best = key;
                    }
                }
            }
        } else {
            // 32 rows per warp unit
            int u_next;
            if (lane == 0) u_next = atomicAdd(&g_pos[t], 32);
            u_next = __shfl_sync(0xffffffffu, u_next, 0);
            while (u_next < VV) {
                int u = u_next;
                if (lane == 0) u_next = atomicAdd(&g_pos[t], 32);
                u_next = __shfl_sync(0xffffffffu, u_next, 0);
                int v0 = u + grp * 8;
                uint4 qq[8];
#pragma unroll
                for (int r = 0; r < 8; r++)
                    qq[r] = __ldcg(&g_embh4[(size_t)(v0 + r) * 8 + l8]);
#pragma unroll
                for (int r = 0; r < 8; r++) {
                    float dot = dot8h(qq[r], xa, xb);
                    dot += __shfl_xor_sync(0xffffffffu, dot, 1);
                    dot += __shfl_xor_sync(0xffffffffu, dot, 2);
                    dot += __shfl_xor_sync(0xffffffffu, dot, 4);
                    if (l8 == 0) {
                        int v = v0 + r;
                        __stcg(&orow[v], dot);
                        unsigned long long key =
                            ((unsigned long long)fkey(dot) << 32) | (0xFFFFFFFFu - (unsigned)v);
                        if (key > best) best = key;
                    }
                }
            }
        }

        sbs[tid] = best;
        __syncthreads();
        for (int o2 = NT / 2; o2; o2 >>= 1) {
            if (tid < o2) { if (sbs[tid + o2] > sbs[tid]) sbs[tid] = sbs[tid + o2]; }
            __syncthreads();
        }
        if (tid == 0) {
            atomicMax(&g_amax[t], sbs[0]);
            __threadfence();
            atomicAdd(&g_done, 1);
        }
    }

    // tail: write generated indices
    if (blk == 0 && tid == 0) {
        while (*(volatile int*)&g_done < NB * STEPS) __nanosleep(64);
        g_gen[STEPS - 1] = dec_idx(__ldcg(&g_amax[STEPS - 1]));
        if (out_size >= STEPS * VV + STEPS)
            for (int i = 0; i < STEPS; i++)
                out[(size_t)STEPS * VV + i] = (float)__ldcg(&g_gen[i]);
    }
}

extern "C" void kernel_launch(void* const* d_in, const int* in_sizes, int n_in,
                              void* d_out, int out_size) {
    const float* ht  = (const float*)d_in[0];
    const float* emb = (const float*)d_in[1];
    const float* pos = (const float*)d_in[2];
    const float* ipw = (const float*)d_in[3];
    const float* ipb = (const float*)d_in[4];
    const float* ow  = (const float*)d_in[5];
    const float* ob  = (const float*)d_in[6];
    const float* l1w = (const float*)d_in[7];
    const float* l1b = (const float*)d_in[8];
    const float* l2w = (const float*)d_in[9];
    const float* l2b = (const float*)d_in[10];
    const float* f1w = (const float*)d_in[11];
    const float* f1b = (const float*)d_in[12];
    const float* f2w = (const float*)d_in[13];
    const float* f2b = (const float*)d_in[14];
    float* out = (float*)d_out;

    persist_kernel<<<NB, NT>>>(ht, emb, pos, ipw, ipb, ow, ob, l1w, l1b,
                               l2w, l2b, f1w, f1b, f2w, f2b, out, out_size);
}

// round 6
// speedup vs baseline: 1.0820x; 1.0820x over previous
#include <cuda_runtime.h>
#include <cuda_fp16.h>
#include <cstddef>

#define D 64
#define NH 4
#define DH 16
#define FF 2048
#define VV 1000000
#define STEPS 10
#define EPS 1e-5f
#define NB 148
#define NT 512
#define PB 32

// Persistent device state (reset by block 0 at start of each call).
__device__ float g_y0s[STEPS * STEPS * D];  // per-step ffn0 accumulators (zeroed at init)
__device__ float g_x1b[D];
__device__ float g_y1part[PB * D];
__device__ float g_xf[D];
__device__ unsigned long long g_amax[STEPS];
__device__ int g_gen[STEPS];
__device__ uint4 g_embh4[VV * 8];
__device__ int g_cnt, g_genbar;
__device__ int g_done;   // cumulative scan-done counter
__device__ int g_mini;   // cumulative P1->P2 mini barrier
__device__ int g_p2c;    // cumulative P2-done counter
__device__ int g_ready;  // step ready flag

__device__ __forceinline__ unsigned int fkey(float f) {
    unsigned int u = __float_as_uint(f);
    return (u & 0x80000000u) ? ~u : (u | 0x80000000u);
}
__device__ __forceinline__ int dec_idx(unsigned long long k) {
    return (int)(0xFFFFFFFFu - (unsigned int)(k & 0xFFFFFFFFull));
}
__device__ __forceinline__ float dot4(float4 a, float4 b) {
    return a.x * b.x + a.y * b.y + a.z * b.z + a.w * b.w;
}
__device__ __forceinline__ uint4 pack8(float4 a, float4 b) {
    uint4 o;
    __half2 h;
    h = __floats2half2_rn(a.x, a.y); o.x = *(unsigned int*)&h;
    h = __floats2half2_rn(a.z, a.w); o.y = *(unsigned int*)&h;
    h = __floats2half2_rn(b.x, b.y); o.z = *(unsigned int*)&h;
    h = __floats2half2_rn(b.z, b.w); o.w = *(unsigned int*)&h;
    return o;
}
__device__ __forceinline__ float dot8h(uint4 q, float4 xa, float4 xb) {
    __half2* hp = (__half2*)&q;
    float2 f0 = __half22float2(hp[0]), f1 = __half22float2(hp[1]);
    float2 f2 = __half22float2(hp[2]), f3 = __half22float2(hp[3]);
    return f0.x * xa.x + f0.y * xa.y + f1.x * xa.z + f1.y * xa.w
         + f2.x * xb.x + f2.y * xb.y + f3.x * xb.z + f3.y * xb.w;
}
__device__ __forceinline__ float red8(float v) {
    v += __shfl_xor_sync(0xffffffffu, v, 4);
    v += __shfl_xor_sync(0xffffffffu, v, 2);
    v += __shfl_xor_sync(0xffffffffu, v, 1);
    return v;
}

__device__ __forceinline__ void grid_bar() {
    __syncthreads();
    if (threadIdx.x == 0) {
        volatile int* genp = &g_genbar;
        int gen = *genp;
        __threadfence();
        if (atomicAdd(&g_cnt, 1) == NB - 1) {
            atomicExch(&g_cnt, 0);
            __threadfence();
            *genp = gen + 1;
        } else {
            while (*genp == gen) { __nanosleep(32); }
        }
    }
    __syncthreads();
}

__global__ void __launch_bounds__(NT, 1)
persist_kernel(const float* __restrict__ ht, const float* __restrict__ emb,
               const float* __restrict__ pos, const float* __restrict__ ipw,
               const float* __restrict__ ipb, const float* __restrict__ ow,
               const float* __restrict__ ob, const float* __restrict__ ln1w,
               const float* __restrict__ ln1b, const float* __restrict__ ln2w,
               const float* __restrict__ ln2b, const float* __restrict__ f1w,
               const float* __restrict__ f1b, const float* __restrict__ f2w,
               const float* __restrict__ f2b, float* __restrict__ out,
               int out_size) {
    __shared__ __align__(16) float sA[STEPS * D];
    __shared__ __align__(16) float sQ[STEPS * 3 * D];
    __shared__ __align__(16) float sO[STEPS * D];
    __shared__ float sSC[NH * STEPS * STEPS];
    __shared__ float sST[2 * STEPS + 4];
    __shared__ int sgen[STEPS];
    __shared__ int s_last;
    __shared__ unsigned long long sbs[NT];

    const int tid = threadIdx.x, blk = blockIdx.x;
    const int lane = tid & 31, wrp = tid >> 5;
    const int grp = lane >> 3, l8 = lane & 7;
    const int g8 = tid >> 3, r8 = tid & 7;

    // Static asymmetric scan ranges (units of 16 rows; total 62500 units = 1M rows).
    int bs, be;
    if (blk < PB) { bs = blk * 230; be = bs + 230; }
    else {
        int sb = blk - PB;
        bs = PB * 230 + sb * 475 + (sb < 40 ? sb : 40);
        be = bs + 475 + (sb < 40 ? 1 : 0);
    }

    // ---- init (block 0), then one full barrier ----
    if (blk == 0) {
        if (tid == 0) { g_done = 0; g_mini = 0; g_p2c = 0; g_ready = 0; }
        if (tid < STEPS) g_amax[tid] = 0ull;
        for (int i = tid; i < STEPS * STEPS * D; i += NT) g_y0s[i] = 0.f;
        __threadfence();
    }
    grid_bar();

    for (int t = 0; t < STEPS; t++) {
        const int S = t + 1;

        if (blk < PB) {
            if (t > 0) {
                if (tid == 0) {
                    while (*(volatile int*)&g_done < NB * t) __nanosleep(32);
                }
                __syncthreads();
                __threadfence();
            }
            // ---------------- P1: layer-0 attn (redundant) + ffn0 slice ----
            if (tid < t) {
                int gi;
                if (tid == t - 1) {
                    gi = dec_idx(__ldcg(&g_amax[t - 1]));
                    if (blk == 0) __stcg(&g_gen[t - 1], gi);
                } else {
                    gi = __ldcg(&g_gen[tid]);
                }
                sgen[tid] = gi;
            }
            __syncthreads();
            for (int i = tid; i < S * D; i += NT) {
                int s = i >> 6, d = i & 63;
                float base = (s == 0) ? ht[d] : emb[(size_t)sgen[s - 1] * D + d];
                sA[i] = base + pos[i];
            }
            __syncthreads();
            for (int i = tid; i < S * 3 * D; i += NT) {
                int s = i / 192, j = i % 192;
                const float4* wr = (const float4*)(ipw + (size_t)j * D);
                const float4* xr = (const float4*)(sA + s * D);
                float acc = ipb[j];
#pragma unroll
                for (int k = 0; k < 16; k++) acc += dot4(wr[k], xr[k]);
                sQ[i] = acc;
            }
            __syncthreads();
            for (int i = tid; i < NH * S * S; i += NT) {
                int h = i / (S * S), r = (i / S) % S, c = i % S;
                const float* q = sQ + r * 192 + h * DH;
                const float* k = sQ + c * 192 + D + h * DH;
                float acc = 0.f;
#pragma unroll
                for (int d = 0; d < DH; d++) acc += q[d] * k[d];
                sSC[(h * S + r) * S + c] = acc * 0.25f;
            }
            __syncthreads();
            if (tid < NH * S) {
                float* row = sSC + tid * S;
                float mx = row[0];
                for (int c = 1; c < S; c++) mx = fmaxf(mx, row[c]);
                float sm = 0.f;
                for (int c = 0; c < S; c++) { float e = expf(row[c] - mx); row[c] = e; sm += e; }
                float inv = 1.f / sm;
                for (int c = 0; c < S; c++) row[c] *= inv;
            }
            __syncthreads();
            for (int i = tid; i < S * D; i += NT) {
                int s = i >> 6, col = i & 63, h = col >> 4, d = col & 15;
                const float* a = sSC + (h * S + s) * S;
                float acc = 0.f;
                for (int c = 0; c < S; c++) acc += a[c] * sQ[c * 192 + 2 * D + h * DH + d];
                sO[i] = acc;
            }
            __syncthreads();
            for (int i = tid; i < S * D; i += NT) {
                int s = i >> 6, e = i & 63;
                const float4* wr = (const float4*)(ow + (size_t)e * D);
                const float4* orow = (const float4*)(sO + s * D);
                float acc = ob[e];
#pragma unroll
                for (int k = 0; k < 16; k++) acc += dot4(wr[k], orow[k]);
                sQ[i] = sA[i] + acc;
            }
            __syncthreads();
            if (tid < S) {
                float m = 0.f;
                for (int d = 0; d < D; d++) m += sQ[tid * D + d];
                m *= (1.f / D);
                float vv = 0.f;
                for (int d = 0; d < D; d++) { float df = sQ[tid * D + d] - m; vv += df * df; }
                vv *= (1.f / D);
                sST[tid * 2] = m;
                sST[tid * 2 + 1] = rsqrtf(vv + EPS);
            }
            __syncthreads();
            for (int i = tid; i < S * D; i += NT) {
                int s = i >> 6, d = i & 63;
                sA[i] = (sQ[i] - sST[s * 2]) * sST[s * 2 + 1] * ln1w[d] + ln1b[d];
            }
            __syncthreads();
            {   // ffn0: 64 units per block
                int f = blk * 64 + g8;
                const float4* w1r = (const float4*)(f1w + (size_t)f * D);
                float4 wa = w1r[2 * r8], wb = w1r[2 * r8 + 1];
                float b1 = f1b[f];
                const float4* x4 = (const float4*)sA;
                for (int s = 0; s < S; s++) {
                    float v = red8(dot4(wa, x4[s * 16 + 2 * r8]) + dot4(wb, x4[s * 16 + 2 * r8 + 1]));
                    if (r8 == 0) sO[s * 64 + g8] = fmaxf(v + b1, 0.f);
                }
                __syncthreads();
                const float4* w2r = (const float4*)(f2w + (size_t)g8 * FF + blk * 64);
                float4 va = w2r[2 * r8], vb = w2r[2 * r8 + 1];
                const float4* h4 = (const float4*)sO;
                for (int s = 0; s < S; s++) {
                    float r = red8(dot4(va, h4[s * 16 + 2 * r8]) + dot4(vb, h4[s * 16 + 2 * r8 + 1]));
                    if (r8 == 0) atomicAdd(&g_y0s[t * (STEPS * D) + s * 64 + g8], r);
                }
            }
            // ---- mini barrier among the 32 P blocks ----
            __threadfence();
            __syncthreads();
            if (tid == 0) {
                atomicAdd(&g_mini, 1);
                while (*(volatile int*)&g_mini < PB * (t + 1)) __nanosleep(32);
            }
            __syncthreads();
            __threadfence();

            // ---------------- P2: layer-1 attn last-row (redundant) + ffn1 slice
            for (int i = tid; i < S * D; i += NT)
                sA[i] = sA[i] + __ldcg(&g_y0s[t * (STEPS * D) + i]) + f2b[i & 63];
            __syncthreads();
            if (tid < S) {
                float m = 0.f;
                for (int d = 0; d < D; d++) m += sA[tid * D + d];
                m *= (1.f / D);
                float vv = 0.f;
                for (int d = 0; d < D; d++) { float df = sA[tid * D + d] - m; vv += df * df; }
                vv *= (1.f / D);
                sST[tid * 2] = m;
                sST[tid * 2 + 1] = rsqrtf(vv + EPS);
            }
            __syncthreads();
            for (int i = tid; i < S * D; i += NT) {
                int s = i >> 6, d = i & 63;
                sA[i] = (sA[i] - sST[s * 2]) * sST[s * 2 + 1] * ln2w[d] + ln2b[d];
            }
            __syncthreads();
            for (int i = tid; i < S * 3 * D; i += NT) {
                int s = i / 192, j = i % 192;
                const float4* wr = (const float4*)(ipw + (size_t)(192 + j) * D);
                const float4* xr = (const float4*)(sA + s * D);
                float acc = ipb[192 + j];
#pragma unroll
                for (int k = 0; k < 16; k++) acc += dot4(wr[k], xr[k]);
                sQ[i] = acc;
            }
            __syncthreads();
            if (tid < NH * S) {
                int h = tid / S, c = tid % S;
                const float* q = sQ + (S - 1) * 192 + h * DH;
                const float* k = sQ + c * 192 + D + h * DH;
                float acc = 0.f;
#pragma unroll
                for (int d = 0; d < DH; d++) acc += q[d] * k[d];
                sSC[h * S + c] = acc * 0.25f;
            }
            __syncthreads();
            if (tid < NH) {
                float* row = sSC + tid * S;
                float mx = row[0];
                for (int c = 1; c < S; c++) mx = fmaxf(mx, row[c]);
                float sm = 0.f;
                for (int c = 0; c < S; c++) { float e = expf(row[c] - mx); row[c] = e; sm += e; }
                float inv = 1.f / sm;
                for (int c = 0; c < S; c++) row[c] *= inv;
            }
            __syncthreads();
            if (tid < D) {
                int h = tid >> 4, d = tid & 15;
                const float* a = sSC + h * S;
                float acc = 0.f;
                for (int c = 0; c < S; c++) acc += a[c] * sQ[c * 192 + 2 * D + h * DH + d];
                sO[tid] = acc;
            }
            __syncthreads();
            if (tid < D) {
                const float4* wr = (const float4*)(ow + (size_t)(D + tid) * D);
                const float4* orow = (const float4*)sO;
                float acc = ob[D + tid];
#pragma unroll
                for (int k = 0; k < 16; k++) acc += dot4(wr[k], orow[k]);
                sQ[tid] = sA[(S - 1) * D + tid] + acc;
            }
            __syncthreads();
            if (tid == 0) {
                float m = 0.f;
                for (int d = 0; d < D; d++) m += sQ[d];
                m *= (1.f / D);
                float vv = 0.f;
                for (int d = 0; d < D; d++) { float df = sQ[d] - m; vv += df * df; }
                vv *= (1.f / D);
                sST[20] = m;
                sST[21] = rsqrtf(vv + EPS);
            }
            __syncthreads();
            if (tid < D) {
                float xl = (sQ[tid] - sST[20]) * sST[21] * ln1w[D + tid] + ln1b[D + tid];
                sA[tid] = xl;
                if (blk == 0) __stcg(&g_x1b[tid], xl);
            }
            __syncthreads();
            {   // ffn1 (layer 1), last row -> per-block partial
                int f = blk * 64 + g8;
                const float4* w1r = (const float4*)(f1w + (size_t)FF * D + (size_t)f * D);
                float4 wa = w1r[2 * r8], wb = w1r[2 * r8 + 1];
                const float4* x4 = (const float4*)sA;
                float v = red8(dot4(wa, x4[2 * r8]) + dot4(wb, x4[2 * r8 + 1]));
                if (r8 == 0) sO[g8] = fmaxf(v + f1b[FF + f], 0.f);
                __syncthreads();
                const float4* w2r = (const float4*)(f2w + (size_t)D * FF + (size_t)g8 * FF + blk * 64);
                float4 va = w2r[2 * r8], vb = w2r[2 * r8 + 1];
                const float4* h4 = (const float4*)sO;
                float r = red8(dot4(va, h4[2 * r8]) + dot4(vb, h4[2 * r8 + 1]));
                if (r8 == 0) __stcg(&g_y1part[blk * 64 + g8], r);
            }
            __threadfence();
            __syncthreads();
            if (tid == 0) s_last = atomicAdd(&g_p2c, 1);
            __syncthreads();
            if (s_last == PB * (t + 1) - 1) {
                if (tid < D) {
                    float v = __ldcg(&g_x1b[tid]) + f2b[D + tid];
#pragma unroll
                    for (int b = 0; b < PB; b++) v += __ldcg(&g_y1part[b * 64 + tid]);
                    sQ[tid] = v;
                }
                __syncthreads();
                if (tid == 0) {
                    float m = 0.f;
                    for (int d = 0; d < D; d++) m += sQ[d];
                    m *= (1.f / D);
                    float vv = 0.f;
                    for (int d = 0; d < D; d++) { float df = sQ[d] - m; vv += df * df; }
                    vv *= (1.f / D);
                    sST[0] = m;
                    sST[1] = rsqrtf(vv + EPS);
                }
                __syncthreads();
                if (tid < D)
                    __stcg(&g_xf[tid], (sQ[tid] - sST[0]) * sST[1] * ln2w[D + tid] + ln2b[D + tid]);
                __threadfence();
                __syncthreads();
                if (tid == 0) atomicExch(&g_ready, t + 1);
            }
        }

        // ================= scan phase (all blocks, static asymmetric ranges) ====
        if (tid == 0)
            while (*(volatile int*)&g_ready < t + 1) __nanosleep(32);
        __syncthreads();
        __threadfence();
        if (tid < D) sO[tid] = __ldcg(&g_xf[tid]);
        __syncthreads();

        const float4* xs4 = (const float4*)sO;
        float4 xa = xs4[2 * l8], xb = xs4[2 * l8 + 1];
        unsigned long long best = 0ull;
        float* orow = out + (size_t)t * VV;

        if (t == 0) {
            for (int u = bs + wrp; u < be; u += 16) {
                int v0 = u * 16 + grp * 4;
                float4 av[4], bv[4];
#pragma unroll
                for (int r = 0; r < 4; r++) {
                    const float4* p = (const float4*)(emb + (size_t)(v0 + r) * D);
                    av[r] = __ldcg(p + 2 * l8);
                    bv[r] = __ldcg(p + 2 * l8 + 1);
                }
                float keep = 0.f;
#pragma unroll
                for (int r = 0; r < 4; r++) {
                    __stcg(&g_embh4[(size_t)(v0 + r) * 8 + l8], pack8(av[r], bv[r]));
                    float dot = dot4(av[r], xa) + dot4(bv[r], xb);
                    dot += __shfl_xor_sync(0xffffffffu, dot, 1);
                    dot += __shfl_xor_sync(0xffffffffu, dot, 2);
                    dot += __shfl_xor_sync(0xffffffffu, dot, 4);
                    if (l8 == r) keep = dot;
                }
                if (l8 < 4) {
                    int v = v0 + l8;
                    __stcg(&orow[v], keep);
                    unsigned long long key =
                        ((unsigned long long)fkey(keep) << 32) | (0xFFFFFFFFu - (unsigned)v);
                    if (key > best) best = key;
                }
            }
        } else {
            for (int u = bs + wrp; u < be; u += 16) {
                int v0 = u * 16 + grp * 4;
                uint4 qq[4];
#pragma unroll
                for (int r = 0; r < 4; r++)
                    qq[r] = __ldcg(&g_embh4[(size_t)(v0 + r) * 8 + l8]);
                float keep = 0.f;
#pragma unroll
                for (int r = 0; r < 4; r++) {
                    float dot = dot8h(qq[r], xa, xb);
                    dot += __shfl_xor_sync(0xffffffffu, dot, 1);
                    dot += __shfl_xor_sync(0xffffffffu, dot, 2);
                    dot += __shfl_xor_sync(0xffffffffu, dot, 4);
                    if (l8 == r) keep = dot;
                }
                if (l8 < 4) {
                    int v = v0 + l8;
                    __stcg(&orow[v], keep);
                    unsigned long long key =
                        ((unsigned long long)fkey(keep) << 32) | (0xFFFFFFFFu - (unsigned)v);
                    if (key > best) best = key;
                }
            }
        }

        sbs[tid] = best;
        __syncthreads();
        for (int o2 = NT / 2; o2; o2 >>= 1) {
            if (tid < o2) { if (sbs[tid + o2] > sbs[tid]) sbs[tid] = sbs[tid + o2]; }
            __syncthreads();
        }
        if (tid == 0) {
            atomicMax(&g_amax[t], sbs[0]);
            __threadfence();
            atomicAdd(&g_done, 1);
        }
    }

    if (blk == 0 && tid == 0) {
        while (*(volatile int*)&g_done < NB * STEPS) __nanosleep(32);
        g_gen[STEPS - 1] = dec_idx(__ldcg(&g_amax[STEPS - 1]));
        if (out_size >= STEPS * VV + STEPS)
            for (int i = 0; i < STEPS; i++)
                out[(size_t)STEPS * VV + i] = (float)__ldcg(&g_gen[i]);
    }
}

extern "C" void kernel_launch(void* const* d_in, const int* in_sizes, int n_in,
                              void* d_out, int out_size) {
    const float* ht  = (const float*)d_in[0];
    const float* emb = (const float*)d_in[1];
    const float* pos = (const float*)d_in[2];
    const float* ipw = (const float*)d_in[3];
    const float* ipb = (const float*)d_in[4];
    const float* ow  = (const float*)d_in[5];
    const float* ob  = (const float*)d_in[6];
    const float* l1w = (const float*)d_in[7];
    const float* l1b = (const float*)d_in[8];
    const float* l2w = (const float*)d_in[9];
    const float* l2b = (const float*)d_in[10];
    const float* f1w = (const float*)d_in[11];
    const float* f1b = (const float*)d_in[12];
    const float* f2w = (const float*)d_in[13];
    const float* f2b = (const float*)d_in[14];
    float* out = (float*)d_out;

    persist_kernel<<<NB, NT>>>(ht, emb, pos, ipw, ipb, ow, ob, l1w, l1b,
                               l2w, l2b, f1w, f1b, f2w, f2b, out, out_size);
}

// round 7
// speedup vs baseline: 1.1148x; 1.0303x over previous
#include <cuda_runtime.h>
#include <cuda_fp16.h>
#include <cstddef>

#define D 64
#define NH 4
#define DH 16
#define FF 2048
#define VV 1000000
#define STEPS 10
#define EPS 1e-5f
#define NB 148
#define NT 512
#define PB 32

// Persistent device state.
__device__ float g_y0s[STEPS * STEPS * D];  // per-step ffn0 accumulators (zeroed at init)
__device__ float g_x1b[D];
__device__ float g_y1part[PB * D];
__device__ float g_xf[D];
__device__ unsigned long long g_amax[STEPS];
__device__ int g_gen[STEPS];
__device__ uint4 g_embT[8ull * VV];  // chunk-major fp16 emb: g_embT[j*VV+v] = dims [8j,8j+8) of row v
__device__ int g_cnt, g_genbar;
__device__ int g_done;
__device__ int g_mini;
__device__ int g_p2c;
__device__ int g_ready;

__device__ __forceinline__ unsigned int fkey(float f) {
    unsigned int u = __float_as_uint(f);
    return (u & 0x80000000u) ? ~u : (u | 0x80000000u);
}
__device__ __forceinline__ int dec_idx(unsigned long long k) {
    return (int)(0xFFFFFFFFu - (unsigned int)(k & 0xFFFFFFFFull));
}
__device__ __forceinline__ float dot4(float4 a, float4 b) {
    return a.x * b.x + a.y * b.y + a.z * b.z + a.w * b.w;
}
__device__ __forceinline__ uint4 pack8(float4 a, float4 b) {
    uint4 o;
    __half2 h;
    h = __floats2half2_rn(a.x, a.y); o.x = *(unsigned int*)&h;
    h = __floats2half2_rn(a.z, a.w); o.y = *(unsigned int*)&h;
    h = __floats2half2_rn(b.x, b.y); o.z = *(unsigned int*)&h;
    h = __floats2half2_rn(b.z, b.w); o.w = *(unsigned int*)&h;
    return o;
}
__device__ __forceinline__ float dot8h(uint4 q, float4 xa, float4 xb) {
    __half2* hp = (__half2*)&q;
    float2 f0 = __half22float2(hp[0]), f1 = __half22float2(hp[1]);
    float2 f2 = __half22float2(hp[2]), f3 = __half22float2(hp[3]);
    return f0.x * xa.x + f0.y * xa.y + f1.x * xa.z + f1.y * xa.w
         + f2.x * xb.x + f2.y * xb.y + f3.x * xb.z + f3.y * xb.w;
}
__device__ __forceinline__ float red8(float v) {
    v += __shfl_xor_sync(0xffffffffu, v, 4);
    v += __shfl_xor_sync(0xffffffffu, v, 2);
    v += __shfl_xor_sync(0xffffffffu, v, 1);
    return v;
}

__device__ __forceinline__ void grid_bar() {
    __syncthreads();
    if (threadIdx.x == 0) {
        volatile int* genp = &g_genbar;
        int gen = *genp;
        __threadfence();
        if (atomicAdd(&g_cnt, 1) == NB - 1) {
            atomicExch(&g_cnt, 0);
            __threadfence();
            *genp = gen + 1;
        } else {
            while (*genp == gen) { __nanosleep(32); }
        }
    }
    __syncthreads();
}

__global__ void __launch_bounds__(NT, 1)
persist_kernel(const float* __restrict__ ht, const float* __restrict__ emb,
               const float* __restrict__ pos, const float* __restrict__ ipw,
               const float* __restrict__ ipb, const float* __restrict__ ow,
               const float* __restrict__ ob, const float* __restrict__ ln1w,
               const float* __restrict__ ln1b, const float* __restrict__ ln2w,
               const float* __restrict__ ln2b, const float* __restrict__ f1w,
               const float* __restrict__ f1b, const float* __restrict__ f2w,
               const float* __restrict__ f2b, float* __restrict__ out,
               int out_size) {
    __shared__ __align__(16) float sA[STEPS * D];
    __shared__ __align__(16) float sQ[STEPS * 3 * D];
    __shared__ __align__(16) float sO[STEPS * D];
    __shared__ float sSC[NH * STEPS * STEPS];
    __shared__ float sST[2 * STEPS + 4];
    __shared__ int sgen[STEPS];
    __shared__ int s_last;
    __shared__ unsigned long long sbs[NT];

    const int tid = threadIdx.x, blk = blockIdx.x;
    const int lane = tid & 31, wrp = tid >> 5;
    const int grp = lane >> 3, l8 = lane & 7;
    const int g8 = tid >> 3, r8 = tid & 7;

    // Step-0 partition: 16-row units, total 62500.
    int bs0, be0;
    if (blk < PB) { bs0 = blk * 230; be0 = bs0 + 230; }
    else {
        int sb = blk - PB;
        bs0 = PB * 230 + sb * 475 + (sb < 40 ? sb : 40);
        be0 = bs0 + 475 + (sb < 40 ? 1 : 0);
    }
    // Steps>=1 partition: 32-row units, total 31250.
    int bs1, be1;
    if (blk < PB) { bs1 = blk * 115; be1 = bs1 + 115; }
    else {
        int sb = blk - PB;
        bs1 = PB * 115 + sb * 237 + (sb < 78 ? sb : 78);
        be1 = bs1 + 237 + (sb < 78 ? 1 : 0);
    }

    if (blk == 0) {
        if (tid == 0) { g_done = 0; g_mini = 0; g_p2c = 0; g_ready = 0; }
        if (tid < STEPS) g_amax[tid] = 0ull;
        for (int i = tid; i < STEPS * STEPS * D; i += NT) g_y0s[i] = 0.f;
        __threadfence();
    }
    grid_bar();

    for (int t = 0; t < STEPS; t++) {
        const int S = t + 1;

        if (blk < PB) {
            if (t > 0) {
                if (tid == 0)
                    while (*(volatile int*)&g_done < NB * t) __nanosleep(32);
                __syncthreads();
                __threadfence();
            }
            // -------- P1: layer-0 attn (redundant) + ffn0 slice --------
            if (tid < t) {
                int gi;
                if (tid == t - 1) {
                    gi = dec_idx(__ldcg(&g_amax[t - 1]));
                    if (blk == 0) __stcg(&g_gen[t - 1], gi);
                } else {
                    gi = __ldcg(&g_gen[tid]);
                }
                sgen[tid] = gi;
            }
            __syncthreads();
            for (int i = tid; i < S * D; i += NT) {
                int s = i >> 6, d = i & 63;
                float base = (s == 0) ? ht[d] : emb[(size_t)sgen[s - 1] * D + d];
                sA[i] = base + pos[i];
            }
            __syncthreads();
            for (int i = tid; i < S * 3 * D; i += NT) {
                int s = i / 192, j = i % 192;
                const float4* wr = (const float4*)(ipw + (size_t)j * D);
                const float4* xr = (const float4*)(sA + s * D);
                float acc = ipb[j];
#pragma unroll
                for (int k = 0; k < 16; k++) acc += dot4(wr[k], xr[k]);
                sQ[i] = acc;
            }
            __syncthreads();
            for (int i = tid; i < NH * S * S; i += NT) {
                int h = i / (S * S), r = (i / S) % S, c = i % S;
                const float* q = sQ + r * 192 + h * DH;
                const float* k = sQ + c * 192 + D + h * DH;
                float acc = 0.f;
#pragma unroll
                for (int d = 0; d < DH; d++) acc += q[d] * k[d];
                sSC[(h * S + r) * S + c] = acc * 0.25f;
            }
            __syncthreads();
            if (tid < NH * S) {
                float* row = sSC + tid * S;
                float mx = row[0];
                for (int c = 1; c < S; c++) mx = fmaxf(mx, row[c]);
                float sm = 0.f;
                for (int c = 0; c < S; c++) { float e = expf(row[c] - mx); row[c] = e; sm += e; }
                float inv = 1.f / sm;
                for (int c = 0; c < S; c++) row[c] *= inv;
            }
            __syncthreads();
            for (int i = tid; i < S * D; i += NT) {
                int s = i >> 6, col = i & 63, h = col >> 4, d = col & 15;
                const float* a = sSC + (h * S + s) * S;
                float acc = 0.f;
                for (int c = 0; c < S; c++) acc += a[c] * sQ[c * 192 + 2 * D + h * DH + d];
                sO[i] = acc;
            }
            __syncthreads();
            for (int i = tid; i < S * D; i += NT) {
                int s = i >> 6, e = i & 63;
                const float4* wr = (const float4*)(ow + (size_t)e * D);
                const float4* orow = (const float4*)(sO + s * D);
                float acc = ob[e];
#pragma unroll
                for (int k = 0; k < 16; k++) acc += dot4(wr[k], orow[k]);
                sQ[i] = sA[i] + acc;
            }
            __syncthreads();
            if (tid < S) {
                float m = 0.f;
                for (int d = 0; d < D; d++) m += sQ[tid * D + d];
                m *= (1.f / D);
                float vv = 0.f;
                for (int d = 0; d < D; d++) { float df = sQ[tid * D + d] - m; vv += df * df; }
                vv *= (1.f / D);
                sST[tid * 2] = m;
                sST[tid * 2 + 1] = rsqrtf(vv + EPS);
            }
            __syncthreads();
            for (int i = tid; i < S * D; i += NT) {
                int s = i >> 6, d = i & 63;
                sA[i] = (sQ[i] - sST[s * 2]) * sST[s * 2 + 1] * ln1w[d] + ln1b[d];
            }
            __syncthreads();
            {   // ffn0: 64 units per block
                int f = blk * 64 + g8;
                const float4* w1r = (const float4*)(f1w + (size_t)f * D);
                float4 wa = w1r[2 * r8], wb = w1r[2 * r8 + 1];
                float b1 = f1b[f];
                const float4* x4 = (const float4*)sA;
                for (int s = 0; s < S; s++) {
                    float v = red8(dot4(wa, x4[s * 16 + 2 * r8]) + dot4(wb, x4[s * 16 + 2 * r8 + 1]));
                    if (r8 == 0) sO[s * 64 + g8] = fmaxf(v + b1, 0.f);
                }
                __syncthreads();
                const float4* w2r = (const float4*)(f2w + (size_t)g8 * FF + blk * 64);
                float4 va = w2r[2 * r8], vb = w2r[2 * r8 + 1];
                const float4* h4 = (const float4*)sO;
                for (int s = 0; s < S; s++) {
                    float r = red8(dot4(va, h4[s * 16 + 2 * r8]) + dot4(vb, h4[s * 16 + 2 * r8 + 1]));
                    if (r8 == 0) atomicAdd(&g_y0s[t * (STEPS * D) + s * 64 + g8], r);
                }
            }
            __threadfence();
            __syncthreads();
            if (tid == 0) {
                atomicAdd(&g_mini, 1);
                while (*(volatile int*)&g_mini < PB * (t + 1)) __nanosleep(32);
            }
            __syncthreads();
            __threadfence();

            // -------- P2: layer-1 attn last-row (redundant) + ffn1 slice --------
            for (int i = tid; i < S * D; i += NT)
                sA[i] = sA[i] + __ldcg(&g_y0s[t * (STEPS * D) + i]) + f2b[i & 63];
            __syncthreads();
            if (tid < S) {
                float m = 0.f;
                for (int d = 0; d < D; d++) m += sA[tid * D + d];
                m *= (1.f / D);
                float vv = 0.f;
                for (int d = 0; d < D; d++) { float df = sA[tid * D + d] - m; vv += df * df; }
                vv *= (1.f / D);
                sST[tid * 2] = m;
                sST[tid * 2 + 1] = rsqrtf(vv + EPS);
            }
            __syncthreads();
            for (int i = tid; i < S * D; i += NT) {
                int s = i >> 6, d = i & 63;
                sA[i] = (sA[i] - sST[s * 2]) * sST[s * 2 + 1] * ln2w[d] + ln2b[d];
            }
            __syncthreads();
            for (int i = tid; i < S * 3 * D; i += NT) {
                int s = i / 192, j = i % 192;
                const float4* wr = (const float4*)(ipw + (size_t)(192 + j) * D);
                const float4* xr = (const float4*)(sA + s * D);
                float acc = ipb[192 + j];
#pragma unroll
                for (int k = 0; k < 16; k++) acc += dot4(wr[k], xr[k]);
                sQ[i] = acc;
            }
            __syncthreads();
            if (tid < NH * S) {
                int h = tid / S, c = tid % S;
                const float* q = sQ + (S - 1) * 192 + h * DH;
                const float* k = sQ + c * 192 + D + h * DH;
                float acc = 0.f;
#pragma unroll
                for (int d = 0; d < DH; d++) acc += q[d] * k[d];
                sSC[h * S + c] = acc * 0.25f;
            }
            __syncthreads();
            if (tid < NH) {
                float* row = sSC + tid * S;
                float mx = row[0];
                for (int c = 1; c < S; c++) mx = fmaxf(mx, row[c]);
                float sm = 0.f;
                for (int c = 0; c < S; c++) { float e = expf(row[c] - mx); row[c] = e; sm += e; }
                float inv = 1.f / sm;
                for (int c = 0; c < S; c++) row[c] *= inv;
            }
            __syncthreads();
            if (tid < D) {
                int h = tid >> 4, d = tid & 15;
                const float* a = sSC + h * S;
                float acc = 0.f;
                for (int c = 0; c < S; c++) acc += a[c] * sQ[c * 192 + 2 * D + h * DH + d];
                sO[tid] = acc;
            }
            __syncthreads();
            if (tid < D) {
                const float4* wr = (const float4*)(ow + (size_t)(D + tid) * D);
                const float4* orow = (const float4*)sO;
                float acc = ob[D + tid];
#pragma unroll
                for (int k = 0; k < 16; k++) acc += dot4(wr[k], orow[k]);
                sQ[tid] = sA[(S - 1) * D + tid] + acc;
            }
            __syncthreads();
            if (tid == 0) {
                float m = 0.f;
                for (int d = 0; d < D; d++) m += sQ[d];
                m *= (1.f / D);
                float vv = 0.f;
                for (int d = 0; d < D; d++) { float df = sQ[d] - m; vv += df * df; }
                vv *= (1.f / D);
                sST[20] = m;
                sST[21] = rsqrtf(vv + EPS);
            }
            __syncthreads();
            if (tid < D) {
                float xl = (sQ[tid] - sST[20]) * sST[21] * ln1w[D + tid] + ln1b[D + tid];
                sA[tid] = xl;
                if (blk == 0) __stcg(&g_x1b[tid], xl);
            }
            __syncthreads();
            {   // ffn1 last row -> per-block partial
                int f = blk * 64 + g8;
                const float4* w1r = (const float4*)(f1w + (size_t)FF * D + (size_t)f * D);
                float4 wa = w1r[2 * r8], wb = w1r[2 * r8 + 1];
                const float4* x4 = (const float4*)sA;
                float v = red8(dot4(wa, x4[2 * r8]) + dot4(wb, x4[2 * r8 + 1]));
                if (r8 == 0) sO[g8] = fmaxf(v + f1b[FF + f], 0.f);
                __syncthreads();
                const float4* w2r = (const float4*)(f2w + (size_t)D * FF + (size_t)g8 * FF + blk * 64);
                float4 va = w2r[2 * r8], vb = w2r[2 * r8 + 1];
                const float4* h4 = (const float4*)sO;
                float r = red8(dot4(va, h4[2 * r8]) + dot4(vb, h4[2 * r8 + 1]));
                if (r8 == 0) __stcg(&g_y1part[blk * 64 + g8], r);
            }
            __threadfence();
            __syncthreads();
            if (tid == 0) s_last = atomicAdd(&g_p2c, 1);
            __syncthreads();
            if (s_last == PB * (t + 1) - 1) {
                if (tid < D) {
                    float v = __ldcg(&g_x1b[tid]) + f2b[D + tid];
#pragma unroll
                    for (int b = 0; b < PB; b++) v += __ldcg(&g_y1part[b * 64 + tid]);
                    sQ[tid] = v;
                }
                __syncthreads();
                if (tid == 0) {
                    float m = 0.f;
                    for (int d = 0; d < D; d++) m += sQ[d];
                    m *= (1.f / D);
                    float vv = 0.f;
                    for (int d = 0; d < D; d++) { float df = sQ[d] - m; vv += df * df; }
                    vv *= (1.f / D);
                    sST[0] = m;
                    sST[1] = rsqrtf(vv + EPS);
                }
                __syncthreads();
                if (tid < D)
                    __stcg(&g_xf[tid], (sQ[tid] - sST[0]) * sST[1] * ln2w[D + tid] + ln2b[D + tid]);
                __threadfence();
                __syncthreads();
                if (tid == 0) atomicExch(&g_ready, t + 1);
            }
        }

        // ================= scan phase =================
        if (tid == 0)
            while (*(volatile int*)&g_ready < t + 1) __nanosleep(32);
        __syncthreads();
        __threadfence();
        if (tid < D) sO[tid] = __ldcg(&g_xf[tid]);
        __syncthreads();

        const float4* xs4 = (const float4*)sO;
        unsigned long long best = 0ull;
        float* orow = out + (size_t)t * VV;

        if (t == 0) {
            // fp32 read (grouped), write transposed fp16 copy.
            float4 xa = xs4[2 * l8], xb = xs4[2 * l8 + 1];
            for (int u = bs0 + wrp; u < be0; u += 16) {
                int v0 = u * 16 + grp * 4;
                float4 av[4], bv[4];
#pragma unroll
                for (int r = 0; r < 4; r++) {
                    const float4* p = (const float4*)(emb + (size_t)(v0 + r) * D);
                    av[r] = __ldcg(p + 2 * l8);
                    bv[r] = __ldcg(p + 2 * l8 + 1);
                }
                float keep = 0.f;
#pragma unroll
                for (int r = 0; r < 4; r++) {
                    __stcg(&g_embT[(size_t)l8 * VV + v0 + r], pack8(av[r], bv[r]));
                    float dot = dot4(av[r], xa) + dot4(bv[r], xb);
                    dot += __shfl_xor_sync(0xffffffffu, dot, 1);
                    dot += __shfl_xor_sync(0xffffffffu, dot, 2);
                    dot += __shfl_xor_sync(0xffffffffu, dot, 4);
                    if (l8 == r) keep = dot;
                }
                if (l8 < 4) {
                    int v = v0 + l8;
                    __stcg(&orow[v], keep);
                    unsigned long long key =
                        ((unsigned long long)fkey(keep) << 32) | (0xFFFFFFFFu - (unsigned)v);
                    if (key > best) best = key;
                }
            }
        } else {
            // chunk-major scan: 1 row per lane, 8 independent coalesced loads, no shuffles.
            float4 xv[16];
#pragma unroll
            for (int k = 0; k < 16; k++) xv[k] = xs4[k];
            for (int u = bs1 + wrp; u < be1; u += 16) {
                int v = u * 32 + lane;
                uint4 q[8];
#pragma unroll
                for (int j = 0; j < 8; j++)
                    q[j] = __ldcg(&g_embT[(size_t)j * VV + v]);
                float dot = 0.f;
#pragma unroll
                for (int j = 0; j < 8; j++)
                    dot += dot8h(q[j], xv[2 * j], xv[2 * j + 1]);
                __stcg(&orow[v], dot);
                unsigned long long key =
                    ((unsigned long long)fkey(dot) << 32) | (0xFFFFFFFFu - (unsigned)v);
                if (key > best) best = key;
            }
        }

        sbs[tid] = best;
        __syncthreads();
        for (int o2 = NT / 2; o2; o2 >>= 1) {
            if (tid < o2) { if (sbs[tid + o2] > sbs[tid]) sbs[tid] = sbs[tid + o2]; }
            __syncthreads();
        }
        if (tid == 0) {
            atomicMax(&g_amax[t], sbs[0]);
            __threadfence();
            atomicAdd(&g_done, 1);
        }
    }

    if (blk == 0 && tid == 0) {
        while (*(volatile int*)&g_done < NB * STEPS) __nanosleep(32);
        g_gen[STEPS - 1] = dec_idx(__ldcg(&g_amax[STEPS - 1]));
        if (out_size >= STEPS * VV + STEPS)
            for (int i = 0; i < STEPS; i++)
                out[(size_t)STEPS * VV + i] = (float)__ldcg(&g_gen[i]);
    }
}

extern "C" void kernel_launch(void* const* d_in, const int* in_sizes, int n_in,
                              void* d_out, int out_size) {
    const float* ht  = (const float*)d_in[0];
    const float* emb = (const float*)d_in[1];
    const float* pos = (const float*)d_in[2];
    const float* ipw = (const float*)d_in[3];
    const float* ipb = (const float*)d_in[4];
    const float* ow  = (const float*)d_in[5];
    const float* ob  = (const float*)d_in[6];
    const float* l1w = (const float*)d_in[7];
    const float* l1b = (const float*)d_in[8];
    const float* l2w = (const float*)d_in[9];
    const float* l2b = (const float*)d_in[10];
    const float* f1w = (const float*)d_in[11];
    const float* f1b = (const float*)d_in[12];
    const float* f2w = (const float*)d_in[13];
    const float* f2b = (const float*)d_in[14];
    float* out = (float*)d_out;

    persist_kernel<<<NB, NT>>>(ht, emb, pos, ipw, ipb, ow, ob, l1w, l1b,
                               l2w, l2b, f1w, f1b, f2w, f2b, out, out_size);
}